// round 16
// baseline (speedup 1.0000x reference)
#include <cuda_runtime.h>
#include <cstdint>

#define NN 8000
#define NE 128000
#define FF 128
#define ZZ 10

#define SQ3f      1.7320508075688772f
#define INV_SQ3   0.5773502691896258f
#define INV_SQF   0.08838834764831845f    // 1/sqrt(128)
#define INV_SQR   0.35355339059327373f    // 1/sqrt(8)
#define INV_SQZ   0.31622776601683794f
#define INV_SQFZ  0.027950849718747374f   // 1/(sqrt(128)*sqrt(10))
#define EPSf      0.25f

// ---------------- scratch (device globals; no allocation allowed) -------------
__device__ float g_x0[NN * FF];
__device__ float g_x1[3 * NN * FF];     // SoA: [comp][node][f]
__device__ float g_a0[NN * FF];
__device__ float g_a1[3 * NN * FF];     // SoA: [comp][node][f]
__device__ uint32_t g_w4bh[32 * 640];   // bf16 hi pairs
__device__ uint32_t g_w4bl[32 * 640];   // bf16 lo (residual) pairs
__device__ int   g_cnt[ZZ];
__device__ int   g_fill[ZZ];
__device__ int   g_off[ZZ];
__device__ int   g_bucket[NN];
__device__ int   g_rcnt[NN];
__device__ int   g_rfill[NN];
__device__ int   g_roff[NN];
__device__ int   g_eorder[NE];

#define X1(c, i) g_x1[(c) * (NN * FF) + (i)]
#define A1(c, i) g_a1[(c) * (NN * FF) + (i)]

__device__ __forceinline__ float silu(float x) {
    return x / (1.f + __expf(-x));
}

__device__ __forceinline__ uint32_t pack_bf16x2(float v_lo, float v_hi) {
    uint32_t r;
    asm("cvt.rn.bf16x2.f32 %0, %1, %2;" : "=r"(r) : "f"(v_hi), "f"(v_lo));
    return r;
}

__device__ __forceinline__ void mma_bf16(float c[4],
                                         uint32_t a0, uint32_t a1, uint32_t a2, uint32_t a3,
                                         uint32_t b0, uint32_t b1) {
    asm volatile(
        "mma.sync.aligned.m16n8k16.row.col.f32.bf16.bf16.f32 "
        "{%0,%1,%2,%3}, {%4,%5,%6,%7}, {%8,%9}, {%0,%1,%2,%3};\n"
        : "+f"(c[0]), "+f"(c[1]), "+f"(c[2]), "+f"(c[3])
        : "r"(a0), "r"(a1), "r"(a2), "r"(a3), "r"(b0), "r"(b1));
}

__device__ __forceinline__ void cp_async16(uint32_t dst, const void* src) {
    asm volatile("cp.async.cg.shared.global [%0], [%1], 16;" :: "r"(dst), "l"(src));
}
__device__ __forceinline__ void cp_commit() {
    asm volatile("cp.async.commit_group;");
}
template <int N>
__device__ __forceinline__ void cp_wait() {
    asm volatile("cp.async.wait_group %0;" :: "n"(N));
}

#define FMA4(accv, v4, wA, wB, wC, wD) \
    accv = fmaf((v4).x, wA, fmaf((v4).y, wB, fmaf((v4).z, wC, fmaf((v4).w, wD, accv))))

// ---------------- setup0: zero everything -------------------------------------
__global__ void setup0_kernel() {
    int i = blockIdx.x * blockDim.x + threadIdx.x;
    int stride = gridDim.x * blockDim.x;
    float4 z4 = make_float4(0.f, 0.f, 0.f, 0.f);
    float4* a0v = (float4*)g_a0;
    float4* a1v = (float4*)g_a1;
    for (int k = i; k < NN * FF / 4; k += stride)     a0v[k] = z4;
    for (int k = i; k < 3 * NN * FF / 4; k += stride) a1v[k] = z4;
    for (int k = i; k < NN; k += stride) { g_rcnt[k] = 0; g_rfill[k] = 0; }
    if (i < ZZ) { g_cnt[i] = 0; g_fill[i] = 0; }
}

// ---------------- setup1: parallel histograms ---------------------------------
__global__ void setup1_kernel(const int* __restrict__ receivers,
                              const int* __restrict__ species) {
    int i = blockIdx.x * blockDim.x + threadIdx.x;
    int stride = gridDim.x * blockDim.x;
    for (int k = i; k < NE; k += stride) atomicAdd(&g_rcnt[receivers[k]], 1);
    for (int k = i; k < NN; k += stride) atomicAdd(&g_cnt[species[k]], 1);
}

// ---------------- setup2: scans -------------------------------------------------
__global__ void __launch_bounds__(1024) setup2_kernel() {
    __shared__ int part[1024];
    const int t = threadIdx.x;
    int s = 0;
#pragma unroll
    for (int i = 0; i < 8; i++) {
        int b = t * 8 + i;
        if (b < NN) s += g_rcnt[b];
    }
    part[t] = s;
    __syncthreads();
    if (t == 0) {
        int acc = 0;
        for (int i = 0; i < 1024; i++) { int v = part[i]; part[i] = acc; acc += v; }
        int za = 0;
        for (int z = 0; z < ZZ; z++) { g_off[z] = za; za += g_cnt[z]; }
    }
    __syncthreads();
    int acc = part[t];
#pragma unroll
    for (int i = 0; i < 8; i++) {
        int b = t * 8 + i;
        if (b < NN) { g_roff[b] = acc; acc += g_rcnt[b]; }
    }
}

// ---------------- mega: rfill | w4prep | fill | up (edge_pre moved out) -------
#define RF_BLOCKS 500
#define W4_BLOCKS 80
#define FS_BLOCKS 32
#define UP_BLOCKS 1000
#define MEGA_BLOCKS (RF_BLOCKS + W4_BLOCKS + FS_BLOCKS + UP_BLOCKS)

__global__ void __launch_bounds__(256) mega_kernel(
    const float* __restrict__ mw4,
    const int* __restrict__ receivers, const int* __restrict__ species,
    const float* __restrict__ nf0, const float* __restrict__ nf1,
    const float* __restrict__ wu0, const float* __restrict__ wu1)
{
    __shared__ __align__(16) float smbuf[4096];
    const int b = blockIdx.x;
    const int t = threadIdx.x;

    if (b < RF_BLOCKS) {
        // ---------- rfill ----------
        int i = b * 256 + t;
        if (i < NE) {
            int r = receivers[i];
            int pos = g_roff[r] + atomicAdd(&g_rfill[r], 1);
            g_eorder[pos] = i;
        }
    } else if (b < RF_BLOCKS + W4_BLOCKS) {
        // ---------- w4prep: packed bf16 hi/lo, k pairs ----------
        int i = (b - RF_BLOCKS) * 256 + t;
        if (i < 32 * 640) {
            int k2 = i / 640, n = i % 640;
            float v0 = mw4[(2 * k2) * 640 + n];
            float v1 = mw4[(2 * k2 + 1) * 640 + n];
            uint32_t h = pack_bf16x2(v0, v1);
            float h0 = __uint_as_float(h << 16);
            float h1 = __uint_as_float(h & 0xffff0000u);
            uint32_t l = pack_bf16x2(v0 - h0, v1 - h1);
            g_w4bh[i] = h;
            g_w4bl[i] = l;
        }
    } else if (b < RF_BLOCKS + W4_BLOCKS + FS_BLOCKS) {
        // ---------- species fill ----------
        int i = (b - RF_BLOCKS - W4_BLOCKS) * 256 + t;
        if (i < NN) {
            int sp = species[i];
            int pos = g_off[sp] + atomicAdd(&g_fill[sp], 1);
            g_bucket[pos] = i;
        }
    } else {
        // ---------- linear_up: 8 nodes/block ----------
        float* s0 = smbuf;               // 8*128 = 1024
        float* s1x = smbuf + 1024;
        float* s1y = smbuf + 2048;
        float* s1z = smbuf + 3072;

        const int ub = b - (RF_BLOCKS + W4_BLOCKS + FS_BLOCKS);
        const int n0 = ub * 8;

        for (int idx = t; idx < 8 * 128; idx += 256) s0[idx] = nf0[n0 * 128 + idx];
        for (int idx = t; idx < 8 * 384; idx += 256) {
            int n = idx / 384, rem = idx % 384;
            int f = rem / 3, c = rem % 3;
            float v = nf1[n0 * 384 + idx];
            if (c == 0) s1x[n * 128 + f] = v;
            else if (c == 1) s1y[n * 128 + f] = v;
            else s1z[n * 128 + f] = v;
        }
        __syncthreads();

        const int ch = t & 127;
        const int h = t >> 7;

        float a0[4], ax[4], ay[4], az[4];
#pragma unroll
        for (int j = 0; j < 4; j++) { a0[j] = ax[j] = ay[j] = az[j] = 0.f; }

        for (int f = 0; f < 128; f += 4) {
            float wA0 = wu0[(f + 0) * 128 + ch], wA1 = wu0[(f + 1) * 128 + ch];
            float wA2 = wu0[(f + 2) * 128 + ch], wA3 = wu0[(f + 3) * 128 + ch];
            float wB0 = wu1[(f + 0) * 128 + ch], wB1 = wu1[(f + 1) * 128 + ch];
            float wB2 = wu1[(f + 2) * 128 + ch], wB3 = wu1[(f + 3) * 128 + ch];
#pragma unroll
            for (int j = 0; j < 4; j++) {
                int jj = h * 4 + j;
                float4 q0 = *(const float4*)&s0[jj * 128 + f];
                FMA4(a0[j], q0, wA0, wA1, wA2, wA3);
                float4 qx = *(const float4*)&s1x[jj * 128 + f];
                FMA4(ax[j], qx, wB0, wB1, wB2, wB3);
                float4 qy = *(const float4*)&s1y[jj * 128 + f];
                FMA4(ay[j], qy, wB0, wB1, wB2, wB3);
                float4 qz = *(const float4*)&s1z[jj * 128 + f];
                FMA4(az[j], qz, wB0, wB1, wB2, wB3);
            }
        }
#pragma unroll
        for (int j = 0; j < 4; j++) {
            int n = n0 + h * 4 + j;
            g_x0[n * 128 + ch] = a0[j] * INV_SQF;
            X1(0, n * 128 + ch) = ax[j] * INV_SQF;
            X1(1, n * 128 + ch) = ay[j] * INV_SQF;
            X1(2, n * 128 + ch) = az[j] * INV_SQF;
        }
    }
}

// ---------------- edge_mma: fused radial MLP + bf16 layer4 + TP + scatter -----
// smem layout (bytes):
//   APH [32][36] u32 @ 0      (4608)
//   APL [32][36] u32 @ 4608   (4608)
//   B bufs: 2 x (Bh[8][648]+Bl[8][648]) @ 9216  (82944); CS overlays after k-loop
//   meta @ 92160 (y1s 384, snd 128, rcv 128, eord 128)
//   MLP scratch @ 92928: mlpA 8192, mlpB 8192, rad 1024
#define APH_OFF 0
#define APL_OFF 4608
#define B_OFF   9216
#define B_HALF  20736                    // 8*648*4
#define B_BUF   41472                    // hi+lo
#define CS_OFF  9216
#define META_OFF 92160
#define SCR_OFF  92928
#define EMM_SMEM (SCR_OFF + 8192 + 8192 + 1024)   // 110336

__global__ void __launch_bounds__(512, 2) edge_mma_kernel(
    const float* __restrict__ vectors,
    const int* __restrict__ senders, const int* __restrict__ receivers,
    const float* __restrict__ radial,
    const float* __restrict__ mw1, const float* __restrict__ mw2,
    const float* __restrict__ mw3)
{
    extern __shared__ char smem[];
    uint32_t* APH = (uint32_t*)(smem + APH_OFF);
    uint32_t* APL = (uint32_t*)(smem + APL_OFF);
    float*    CS  = (float*)(smem + CS_OFF);
    float*    y1s = (float*)(smem + META_OFF);
    int*      snd = (int*)(smem + META_OFF + 384);
    int*      rcv = (int*)(smem + META_OFF + 384 + 128);
    int*      eord = (int*)(smem + META_OFF + 384 + 256);
    float*    mlpA = (float*)(smem + SCR_OFF);
    float*    mlpB = (float*)(smem + SCR_OFF + 8192);
    float*    rads = (float*)(smem + SCR_OFF + 16384);

    const int t = threadIdx.x;
    const int e_base = blockIdx.x * 32;
    const uint32_t smem_u32 = (uint32_t)__cvta_generic_to_shared(smem);

    if (t < 32) {
        int oe = g_eorder[e_base + t];
        eord[t] = oe;
        snd[t] = senders[oe];
        rcv[t] = receivers[oe];
        float vx = vectors[oe * 3 + 0], vy = vectors[oe * 3 + 1], vz = vectors[oe * 3 + 2];
        float rn = sqrtf(vx * vx + vy * vy + vz * vz) + 1e-12f;
        float sc = SQ3f / rn;
        y1s[t * 3 + 0] = vx * sc;
        y1s[t * 3 + 1] = vy * sc;
        y1s[t * 3 + 2] = vz * sc;
    }

    // B slab-0 prefetch FIRST: overlaps the whole MLP phase below
    {
#pragma unroll
        for (int i = 0; i < 3; i++) {
            int idx = t + i * 512;
            if (idx < 1280) {
                int r = idx / 160, c = idx % 160;
                uint32_t dh = smem_u32 + B_OFF + (r * 648 + c * 4) * 4;
                cp_async16(dh, g_w4bh + r * 640 + c * 4);
                cp_async16(dh + B_HALF, g_w4bl + r * 640 + c * 4);
            }
        }
        cp_commit();
    }
    __syncthreads();   // eord visible

    // ---- fused radial MLP (layers 1-3), 32 sorted edges ----
    if (t < 256) rads[t] = radial[eord[t >> 3] * 8 + (t & 7)];
    __syncthreads();

    const int j64 = t & 63;
    const int egp = t >> 6;          // 0..7, 4 edges each

    // layer 1: [8 -> 64]
#pragma unroll
    for (int e4 = 0; e4 < 4; e4++) {
        int e = egp * 4 + e4;
        float acc = 0.f;
#pragma unroll
        for (int k = 0; k < 8; k++) acc = fmaf(rads[e * 8 + k], mw1[k * 64 + j64], acc);
        mlpA[e * 64 + j64] = silu(acc * INV_SQR);
    }
    __syncthreads();

    // layer 2: mlpA -> mlpB
    {
        float acc[4];
#pragma unroll
        for (int e4 = 0; e4 < 4; e4++) acc[e4] = 0.f;
        for (int k = 0; k < 64; k += 4) {
            float w_0 = mw2[(k + 0) * 64 + j64], w_1 = mw2[(k + 1) * 64 + j64];
            float w_2 = mw2[(k + 2) * 64 + j64], w_3 = mw2[(k + 3) * 64 + j64];
#pragma unroll
            for (int e4 = 0; e4 < 4; e4++) {
                float4 h = *(const float4*)&mlpA[(egp * 4 + e4) * 64 + k];
                FMA4(acc[e4], h, w_0, w_1, w_2, w_3);
            }
        }
#pragma unroll
        for (int e4 = 0; e4 < 4; e4++)
            mlpB[(egp * 4 + e4) * 64 + j64] = silu(acc[e4] * 0.125f);
    }
    __syncthreads();

    // layer 3: mlpB -> mlpA (h3 stays in smem)
    {
        float acc[4];
#pragma unroll
        for (int e4 = 0; e4 < 4; e4++) acc[e4] = 0.f;
        for (int k = 0; k < 64; k += 4) {
            float w_0 = mw3[(k + 0) * 64 + j64], w_1 = mw3[(k + 1) * 64 + j64];
            float w_2 = mw3[(k + 2) * 64 + j64], w_3 = mw3[(k + 3) * 64 + j64];
#pragma unroll
            for (int e4 = 0; e4 < 4; e4++) {
                float4 h = *(const float4*)&mlpB[(egp * 4 + e4) * 64 + k];
                FMA4(acc[e4], h, w_0, w_1, w_2, w_3);
            }
        }
#pragma unroll
        for (int e4 = 0; e4 < 4; e4++)
            mlpA[(egp * 4 + e4) * 64 + j64] = silu(acc[e4] * 0.125f);
    }
    __syncthreads();

    // ---- stage A from mlpA as packed bf16 hi/lo pairs along k ----
#pragma unroll
    for (int i = 0; i < 2; i++) {
        int idx = t + i * 512;
        int r = idx >> 5, k2 = idx & 31;
        float2 p = *(const float2*)&mlpA[r * 64 + 2 * k2];
        uint32_t h = pack_bf16x2(p.x, p.y);
        float h0 = __uint_as_float(h << 16);
        float h1 = __uint_as_float(h & 0xffff0000u);
        uint32_t l = pack_bf16x2(p.x - h0, p.y - h1);
        APH[r * 36 + k2] = h;
        APL[r * 36 + k2] = l;
    }

    const int warp = t >> 5;
    const int lane = t & 31;
    const int g = lane >> 2;
    const int q = lane & 3;
    const int wm = warp & 1;
    const int wn = warp >> 1;
    const int r0 = wm * 16 + g;

    float acc[10][4];
#pragma unroll
    for (int nt = 0; nt < 10; nt++)
#pragma unroll
        for (int i = 0; i < 4; i++) acc[nt][i] = 0.f;

    for (int s = 0; s < 4; s++) {
        if (s + 1 < 4) {
            const int buf = (s + 1) & 1;
#pragma unroll
            for (int i = 0; i < 3; i++) {
                int idx = t + i * 512;
                if (idx < 1280) {
                    int r = idx / 160, c = idx % 160;
                    uint32_t dh = smem_u32 + B_OFF + buf * B_BUF + (r * 648 + c * 4) * 4;
                    cp_async16(dh, g_w4bh + ((s + 1) * 8 + r) * 640 + c * 4);
                    cp_async16(dh + B_HALF, g_w4bl + ((s + 1) * 8 + r) * 640 + c * 4);
                }
            }
            cp_commit();
            cp_wait<1>();
        } else {
            cp_wait<0>();
        }
        __syncthreads();

        const uint32_t* BH = (const uint32_t*)(smem + B_OFF + (s & 1) * B_BUF);
        const uint32_t* BL = BH + B_HALF / 4;

        const int kq = s * 8 + q;
        uint32_t ah0 = APH[r0 * 36 + kq];
        uint32_t ah1 = APH[(r0 + 8) * 36 + kq];
        uint32_t ah2 = APH[r0 * 36 + kq + 4];
        uint32_t ah3 = APH[(r0 + 8) * 36 + kq + 4];
        uint32_t al0 = APL[r0 * 36 + kq];
        uint32_t al1 = APL[(r0 + 8) * 36 + kq];
        uint32_t al2 = APL[r0 * 36 + kq + 4];
        uint32_t al3 = APL[(r0 + 8) * 36 + kq + 4];

#pragma unroll
        for (int nt = 0; nt < 10; nt++) {
            const int nb = wn * 80 + nt * 8 + g;
            uint32_t bh0 = BH[q * 648 + nb];
            uint32_t bh1 = BH[(q + 4) * 648 + nb];
            uint32_t bl0 = BL[q * 648 + nb];
            uint32_t bl1 = BL[(q + 4) * 648 + nb];
            mma_bf16(acc[nt], ah0, ah1, ah2, ah3, bh0, bh1);
            mma_bf16(acc[nt], ah0, ah1, ah2, ah3, bl0, bl1);
            mma_bf16(acc[nt], al0, al1, al2, al3, bh0, bh1);
        }
        __syncthreads();
    }

    // spill C to smem (overlays B buffers)
#pragma unroll
    for (int nt = 0; nt < 10; nt++) {
        int col = wn * 80 + nt * 8 + 2 * q;
        CS[r0 * 644 + col]           = acc[nt][0];
        CS[r0 * 644 + col + 1]       = acc[nt][1];
        CS[(r0 + 8) * 644 + col]     = acc[nt][2];
        CS[(r0 + 8) * 644 + col + 1] = acc[nt][3];
    }
    __syncthreads();

    // ---- message phase (SoA gathers + run-aggregated SoA atomics) ----
    const int f = t & 127;
    const int eg = t >> 7;

    float A0 = 0.f, A1x = 0.f, A1y = 0.f, A1z = 0.f;
    int cur = -1;

#pragma unroll
    for (int ee = 0; ee < 8; ee++) {
        int el = eg * 8 + ee;
        int sN = snd[el];
        int r = rcv[el];
        float m0  = g_x0[sN * 128 + f];
        float m1x = X1(0, sN * 128 + f);
        float m1y = X1(1, sN * 128 + f);
        float m1z = X1(2, sN * 128 + f);
        float Yx = y1s[el * 3 + 0], Yy = y1s[el * 3 + 1], Yz = y1s[el * 3 + 2];

        const float* crow = CS + el * 644;
        float mix0 = crow[0 * 128 + f] * 0.125f;
        float mix1 = crow[1 * 128 + f] * 0.125f;
        float mix2 = crow[2 * 128 + f] * 0.125f;
        float mix3 = crow[3 * 128 + f] * 0.125f;
        float mix4 = crow[4 * 128 + f] * 0.125f;

        float dotf = (m1x * Yx + m1y * Yy + m1z * Yz) * INV_SQ3;
        float out0 = mix0 * m0 + mix1 * dotf;

        float ox = m0 * Yx * INV_SQ3;
        float oy = m0 * Yy * INV_SQ3;
        float oz = m0 * Yz * INV_SQ3;

        float cx = (m1y * Yz - m1z * Yy) * INV_SQ3;
        float cy = (m1z * Yx - m1x * Yz) * INV_SQ3;
        float cz = (m1x * Yy - m1y * Yx) * INV_SQ3;

        float o1x = mix2 * ox + mix3 * m1x + mix4 * cx;
        float o1y = mix2 * oy + mix3 * m1y + mix4 * cy;
        float o1z = mix2 * oz + mix3 * m1z + mix4 * cz;

        if (r != cur) {
            if (cur >= 0) {
                atomicAdd(&g_a0[cur * 128 + f], EPSf * A0);
                atomicAdd(&A1(0, cur * 128 + f), EPSf * A1x);
                atomicAdd(&A1(1, cur * 128 + f), EPSf * A1y);
                atomicAdd(&A1(2, cur * 128 + f), EPSf * A1z);
            }
            cur = r;
            A0 = A1x = A1y = A1z = 0.f;
        }
        A0 += out0; A1x += o1x; A1y += o1y; A1z += o1z;
    }
    if (cur >= 0) {
        atomicAdd(&g_a0[cur * 128 + f], EPSf * A0);
        atomicAdd(&A1(0, cur * 128 + f), EPSf * A1x);
        atomicAdd(&A1(1, cur * 128 + f), EPSf * A1y);
        atomicAdd(&A1(2, cur * 128 + f), EPSf * A1z);
    }
}

// ---------------- node kernel (R12 proven 128-thread shape) --------------------
__global__ void __launch_bounds__(128) node_kernel(
    const float* __restrict__ nf0, const float* __restrict__ nf1,
    const int* __restrict__ species,
    const float* __restrict__ wz0, const float* __restrict__ wz1,
    const float* __restrict__ wd0, const float* __restrict__ wd1,
    const float* __restrict__ wsc,
    const float* __restrict__ wp0, const float* __restrict__ wp1,
    const float* __restrict__ wr0,
    float* __restrict__ out, int write_feats)
{
    __shared__ __align__(16) float sa0[8 * 128];
    __shared__ __align__(16) float sa1[3][8 * 128];
    __shared__ __align__(16) float sn0[8 * 128];
    __shared__ __align__(16) float sn1[3][8 * 128];
    __shared__ int   snid[8];
    __shared__ int   ssp[8];
    __shared__ float sred[8 * 4];

    const int t = threadIdx.x;
    const int bb = blockIdx.x * 8;

    if (t < 8) {
        int n = g_bucket[bb + t];
        snid[t] = n;
        ssp[t] = species[n];
    }
    __syncthreads();

    bool uni = true;
    int sp0 = ssp[0];
#pragma unroll
    for (int jj = 1; jj < 8; jj++) uni = uni && (ssp[jj] == sp0);

#pragma unroll
    for (int jj = 0; jj < 8; jj++) {
        int n = snid[jj];
        sa0[jj * 128 + t] = g_a0[n * 128 + t];
        sn0[jj * 128 + t] = nf0[n * 128 + t];
#pragma unroll
        for (int c = 0; c < 3; c++) {
            sa1[c][jj * 128 + t] = A1(c, n * 128 + t);
            sn1[c][jj * 128 + t] = nf1[(n * 128 + t) * 3 + c];
        }
    }
    __syncthreads();

    float s[8], vx[8], vy[8], vz[8];
#pragma unroll
    for (int jj = 0; jj < 8; jj++) { s[jj] = vx[jj] = vy[jj] = vz[jj] = 0.f; }

    for (int f = 0; f < 128; f += 4) {
        float wA0 = wd0[(f + 0) * 128 + t], wA1 = wd0[(f + 1) * 128 + t];
        float wA2 = wd0[(f + 2) * 128 + t], wA3 = wd0[(f + 3) * 128 + t];
        float wB0 = wd1[(f + 0) * 128 + t], wB1 = wd1[(f + 1) * 128 + t];
        float wB2 = wd1[(f + 2) * 128 + t], wB3 = wd1[(f + 3) * 128 + t];
#pragma unroll
        for (int jj = 0; jj < 8; jj++) {
            float4 q0 = *(const float4*)&sa0[jj * 128 + f];
            FMA4(s[jj], q0, wA0, wA1, wA2, wA3);
            float4 qx = *(const float4*)&sa1[0][jj * 128 + f];
            FMA4(vx[jj], qx, wB0, wB1, wB2, wB3);
            float4 qy = *(const float4*)&sa1[1][jj * 128 + f];
            FMA4(vy[jj], qy, wB0, wB1, wB2, wB3);
            float4 qz = *(const float4*)&sa1[2][jj * 128 + f];
            FMA4(vz[jj], qz, wB0, wB1, wB2, wB3);
        }
    }

    float c0[8], cx[8], cy[8], cz[8];
#pragma unroll
    for (int jj = 0; jj < 8; jj++) { c0[jj] = cx[jj] = cy[jj] = cz[jj] = 0.f; }

    if (uni) {
        const float* z0 = wz0 + sp0 * (128 * 128);
        const float* z1 = wz1 + sp0 * (128 * 128);
        for (int f = 0; f < 128; f += 4) {
            float zA0 = z0[(f + 0) * 128 + t], zA1 = z0[(f + 1) * 128 + t];
            float zA2 = z0[(f + 2) * 128 + t], zA3 = z0[(f + 3) * 128 + t];
            float zB0 = z1[(f + 0) * 128 + t], zB1 = z1[(f + 1) * 128 + t];
            float zB2 = z1[(f + 2) * 128 + t], zB3 = z1[(f + 3) * 128 + t];
#pragma unroll
            for (int jj = 0; jj < 8; jj++) {
                float4 q0 = *(const float4*)&sn0[jj * 128 + f];
                FMA4(c0[jj], q0, zA0, zA1, zA2, zA3);
                float4 qx = *(const float4*)&sn1[0][jj * 128 + f];
                FMA4(cx[jj], qx, zB0, zB1, zB2, zB3);
                float4 qy = *(const float4*)&sn1[1][jj * 128 + f];
                FMA4(cy[jj], qy, zB0, zB1, zB2, zB3);
                float4 qz = *(const float4*)&sn1[2][jj * 128 + f];
                FMA4(cz[jj], qz, zB0, zB1, zB2, zB3);
            }
        }
    } else {
        for (int jj = 0; jj < 8; jj++) {
            const float* z0 = wz0 + ssp[jj] * (128 * 128);
            const float* z1 = wz1 + ssp[jj] * (128 * 128);
            for (int f = 0; f < 128; f += 4) {
                float zA0 = z0[(f + 0) * 128 + t], zA1 = z0[(f + 1) * 128 + t];
                float zA2 = z0[(f + 2) * 128 + t], zA3 = z0[(f + 3) * 128 + t];
                float zB0 = z1[(f + 0) * 128 + t], zB1 = z1[(f + 1) * 128 + t];
                float zB2 = z1[(f + 2) * 128 + t], zB3 = z1[(f + 3) * 128 + t];
                float4 q0 = *(const float4*)&sn0[jj * 128 + f];
                FMA4(c0[jj], q0, zA0, zA1, zA2, zA3);
                float4 qx = *(const float4*)&sn1[0][jj * 128 + f];
                FMA4(cx[jj], qx, zB0, zB1, zB2, zB3);
                float4 qy = *(const float4*)&sn1[1][jj * 128 + f];
                FMA4(cy[jj], qy, zB0, zB1, zB2, zB3);
                float4 qz = *(const float4*)&sn1[2][jj * 128 + f];
                FMA4(cz[jj], qz, zB0, zB1, zB2, zB3);
            }
        }
    }
    __syncthreads();

#pragma unroll
    for (int jj = 0; jj < 8; jj++) {
        sn0[jj * 128 + t]    = c0[jj];
        sn1[0][jj * 128 + t] = cx[jj];
        sn1[1][jj * 128 + t] = cy[jj];
        sn1[2][jj * 128 + t] = cz[jj];
    }

#pragma unroll
    for (int jj = 0; jj < 8; jj++) {
        float sv  = s[jj] * INV_SQF;
        float vxx = vx[jj] * INV_SQF;
        float vyy = vy[jj] * INV_SQF;
        float vzz = vz[jj] * INV_SQF;
        float vv  = vxx * vxx + vyy * vyy + vzz * vzz;
        const float* w = wsc + ssp[jj] * (9 * 128);
        float w0 = w[0 * 128 + t] * INV_SQZ;
        float w1 = w[1 * 128 + t] * INV_SQZ;
        float w2 = w[2 * 128 + t] * INV_SQZ;
        float w3 = w[3 * 128 + t] * INV_SQZ;
        float w4 = w[4 * 128 + t] * INV_SQZ;
        float w5 = w[5 * 128 + t] * INV_SQZ;
        float w6 = w[6 * 128 + t] * INV_SQZ;
        float w7 = w[7 * 128 + t] * INV_SQZ;
        float w8 = w[8 * 128 + t] * INV_SQZ;
        float b0v = w0 * sv + w1 * sv * sv + w2 * vv + w3 * sv * sv * sv + w4 * sv * vv;
        float g1  = w5 + w6 * sv + w7 * sv * sv + w8 * vv;
        sa0[jj * 128 + t]    = b0v;
        sa1[0][jj * 128 + t] = g1 * vxx;
        sa1[1][jj * 128 + t] = g1 * vyy;
        sa1[2][jj * 128 + t] = g1 * vzz;
    }
    __syncthreads();

    float f0[8], f1x[8], f1y[8], f1z[8];
#pragma unroll
    for (int jj = 0; jj < 8; jj++) { f0[jj] = f1x[jj] = f1y[jj] = f1z[jj] = 0.f; }

    for (int f = 0; f < 128; f += 4) {
        float wA0 = wp0[(f + 0) * 128 + t], wA1 = wp0[(f + 1) * 128 + t];
        float wA2 = wp0[(f + 2) * 128 + t], wA3 = wp0[(f + 3) * 128 + t];
        float wB0 = wp1[(f + 0) * 128 + t], wB1 = wp1[(f + 1) * 128 + t];
        float wB2 = wp1[(f + 2) * 128 + t], wB3 = wp1[(f + 3) * 128 + t];
#pragma unroll
        for (int jj = 0; jj < 8; jj++) {
            float4 q0 = *(const float4*)&sa0[jj * 128 + f];
            FMA4(f0[jj], q0, wA0, wA1, wA2, wA3);
            float4 qx = *(const float4*)&sa1[0][jj * 128 + f];
            FMA4(f1x[jj], qx, wB0, wB1, wB2, wB3);
            float4 qy = *(const float4*)&sa1[1][jj * 128 + f];
            FMA4(f1y[jj], qy, wB0, wB1, wB2, wB3);
            float4 qz = *(const float4*)&sa1[2][jj * 128 + f];
            FMA4(f1z[jj], qz, wB0, wB1, wB2, wB3);
        }
    }

    float wrv = wr0[t];
#pragma unroll
    for (int jj = 0; jj < 8; jj++) {
        int n = snid[jj];
        float F0  = f0[jj]  * INV_SQF + sn0[jj * 128 + t]    * INV_SQFZ;
        float F1x = f1x[jj] * INV_SQF + sn1[0][jj * 128 + t] * INV_SQFZ;
        float F1y = f1y[jj] * INV_SQF + sn1[1][jj * 128 + t] * INV_SQFZ;
        float F1z = f1z[jj] * INV_SQF + sn1[2][jj * 128 + t] * INV_SQFZ;

        if (write_feats) {
            out[NN + n * 128 + t]                      = F0;
            out[NN + NN * 128 + (n * 128 + t) * 3 + 0] = F1x;
            out[NN + NN * 128 + (n * 128 + t) * 3 + 1] = F1y;
            out[NN + NN * 128 + (n * 128 + t) * 3 + 2] = F1z;
        }

        float contrib = F0 * wrv;
#pragma unroll
        for (int off = 16; off > 0; off >>= 1)
            contrib += __shfl_xor_sync(0xffffffffu, contrib, off);
        if ((t & 31) == 0) sred[jj * 4 + (t >> 5)] = contrib;
    }
    __syncthreads();
    if (t < 8) {
        float r = (sred[t * 4 + 0] + sred[t * 4 + 1] + sred[t * 4 + 2] + sred[t * 4 + 3]) * INV_SQF;
        out[snid[t]] = r;
    }
}

// ---------------- launch ------------------------------------------------------
extern "C" void kernel_launch(void* const* d_in, const int* in_sizes, int n_in,
                              void* d_out, int out_size)
{
    const float* vectors   = (const float*)d_in[0];
    const float* nf0       = (const float*)d_in[1];
    const float* nf1       = (const float*)d_in[2];
    const float* radial    = (const float*)d_in[3];
    const int*   species   = (const int*)d_in[4];
    const int*   senders   = (const int*)d_in[5];
    const int*   receivers = (const int*)d_in[6];
    const float* wz0       = (const float*)d_in[7];
    const float* wz1       = (const float*)d_in[8];
    const float* wu0       = (const float*)d_in[9];
    const float* wu1       = (const float*)d_in[10];
    const float* mw1       = (const float*)d_in[11];
    const float* mw2       = (const float*)d_in[12];
    const float* mw3       = (const float*)d_in[13];
    const float* mw4       = (const float*)d_in[14];
    const float* wd0       = (const float*)d_in[15];
    const float* wd1       = (const float*)d_in[16];
    const float* wsc       = (const float*)d_in[17];
    const float* wp0       = (const float*)d_in[18];
    const float* wp1       = (const float*)d_in[19];
    const float* wr0       = (const float*)d_in[20];
    float* out = (float*)d_out;

    int write_feats = (out_size >= NN * (1 + 4 * FF)) ? 1 : 0;

    cudaFuncSetAttribute(edge_mma_kernel,
                         cudaFuncAttributeMaxDynamicSharedMemorySize, EMM_SMEM);

    setup0_kernel<<<1024, 256>>>();                                 // 1
    setup1_kernel<<<512, 256>>>(receivers, species);                // 2
    setup2_kernel<<<1, 1024>>>();                                   // 3
    mega_kernel<<<MEGA_BLOCKS, 256>>>(mw4, receivers, species,
                                      nf0, nf1, wu0, wu1);          // 4 <- ncu
    edge_mma_kernel<<<NE / 32, 512, EMM_SMEM>>>(vectors, senders, receivers,
                                                radial, mw1, mw2, mw3);  // 5
    node_kernel<<<NN / 8, 128>>>(nf0, nf1, species, wz0, wz1, wd0, wd1,
                                 wsc, wp0, wp1, wr0, out, write_feats);  // 6
}

// round 17
// speedup vs baseline: 1.0417x; 1.0417x over previous
#include <cuda_runtime.h>
#include <cstdint>

#define NN 8000
#define NE 128000
#define FF 128
#define ZZ 10

#define SQ3f      1.7320508075688772f
#define INV_SQ3   0.5773502691896258f
#define INV_SQF   0.08838834764831845f    // 1/sqrt(128)
#define INV_SQR   0.35355339059327373f    // 1/sqrt(8)
#define INV_SQZ   0.31622776601683794f
#define INV_SQFZ  0.027950849718747374f   // 1/(sqrt(128)*sqrt(10))
#define EPSf      0.25f

// ---------------- scratch (device globals; no allocation allowed) -------------
__device__ float g_x0[NN * FF];
__device__ float g_x1[3 * NN * FF];     // SoA: [comp][node][f]
__device__ float g_a0[NN * FF];
__device__ float g_a1[3 * NN * FF];     // SoA: [comp][node][f]
__device__ float g_h3[NE * 64];
__device__ uint32_t g_w4bh[32 * 640];   // bf16 hi pairs
__device__ uint32_t g_w4bl[32 * 640];   // bf16 lo (residual) pairs
__device__ int   g_cnt[ZZ];
__device__ int   g_fill[ZZ];
__device__ int   g_off[ZZ];
__device__ int   g_bucket[NN];
__device__ int   g_rcnt[NN];
__device__ int   g_rfill[NN];
__device__ int   g_roff[NN];
__device__ int   g_eorder[NE];

#define X1(c, i) g_x1[(c) * (NN * FF) + (i)]
#define A1(c, i) g_a1[(c) * (NN * FF) + (i)]

__device__ __forceinline__ float silu(float x) {
    return x / (1.f + __expf(-x));
}

__device__ __forceinline__ uint32_t pack_bf16x2(float v_lo, float v_hi) {
    uint32_t r;
    asm("cvt.rn.bf16x2.f32 %0, %1, %2;" : "=r"(r) : "f"(v_hi), "f"(v_lo));
    return r;
}

__device__ __forceinline__ void mma_bf16(float c[4],
                                         uint32_t a0, uint32_t a1, uint32_t a2, uint32_t a3,
                                         uint32_t b0, uint32_t b1) {
    asm volatile(
        "mma.sync.aligned.m16n8k16.row.col.f32.bf16.bf16.f32 "
        "{%0,%1,%2,%3}, {%4,%5,%6,%7}, {%8,%9}, {%0,%1,%2,%3};\n"
        : "+f"(c[0]), "+f"(c[1]), "+f"(c[2]), "+f"(c[3])
        : "r"(a0), "r"(a1), "r"(a2), "r"(a3), "r"(b0), "r"(b1));
}

__device__ __forceinline__ void cp_async16(uint32_t dst, const void* src) {
    asm volatile("cp.async.cg.shared.global [%0], [%1], 16;" :: "r"(dst), "l"(src));
}
__device__ __forceinline__ void cp_commit() {
    asm volatile("cp.async.commit_group;");
}
template <int N>
__device__ __forceinline__ void cp_wait() {
    asm volatile("cp.async.wait_group %0;" :: "n"(N));
}

#define FMA4(accv, v4, wA, wB, wC, wD) \
    accv = fmaf((v4).x, wA, fmaf((v4).y, wB, fmaf((v4).z, wC, fmaf((v4).w, wD, accv))))

// ---------------- setup0: zero everything -------------------------------------
__global__ void setup0_kernel() {
    int i = blockIdx.x * blockDim.x + threadIdx.x;
    int stride = gridDim.x * blockDim.x;
    float4 z4 = make_float4(0.f, 0.f, 0.f, 0.f);
    float4* a0v = (float4*)g_a0;
    float4* a1v = (float4*)g_a1;
    for (int k = i; k < NN * FF / 4; k += stride)     a0v[k] = z4;
    for (int k = i; k < 3 * NN * FF / 4; k += stride) a1v[k] = z4;
    for (int k = i; k < NN; k += stride) { g_rcnt[k] = 0; g_rfill[k] = 0; }
    if (i < ZZ) { g_cnt[i] = 0; g_fill[i] = 0; }
}

// ---------------- setup1: parallel histograms ---------------------------------
__global__ void setup1_kernel(const int* __restrict__ receivers,
                              const int* __restrict__ species) {
    int i = blockIdx.x * blockDim.x + threadIdx.x;
    int stride = gridDim.x * blockDim.x;
    for (int k = i; k < NE; k += stride) atomicAdd(&g_rcnt[receivers[k]], 1);
    for (int k = i; k < NN; k += stride) atomicAdd(&g_cnt[species[k]], 1);
}

// ---------------- setup2: scans -------------------------------------------------
__global__ void __launch_bounds__(1024) setup2_kernel() {
    __shared__ int part[1024];
    const int t = threadIdx.x;
    int s = 0;
#pragma unroll
    for (int i = 0; i < 8; i++) {
        int b = t * 8 + i;
        if (b < NN) s += g_rcnt[b];
    }
    part[t] = s;
    __syncthreads();
    if (t == 0) {
        int acc = 0;
        for (int i = 0; i < 1024; i++) { int v = part[i]; part[i] = acc; acc += v; }
        int za = 0;
        for (int z = 0; z < ZZ; z++) { g_off[z] = za; za += g_cnt[z]; }
    }
    __syncthreads();
    int acc = part[t];
#pragma unroll
    for (int i = 0; i < 8; i++) {
        int b = t * 8 + i;
        if (b < NN) { g_roff[b] = acc; acc += g_rcnt[b]; }
    }
}

// ---------------- mega: edge_pre(64) | rfill | w4prep | fill | up -------------
#define EP_BLOCKS 2000
#define RF_BLOCKS 500
#define W4_BLOCKS 80
#define FS_BLOCKS 32
#define UP_BLOCKS 1000
#define MEGA_BLOCKS (EP_BLOCKS + RF_BLOCKS + W4_BLOCKS + FS_BLOCKS + UP_BLOCKS)

__global__ void __launch_bounds__(256) mega_kernel(
    const float* __restrict__ radial,
    const float* __restrict__ mw1, const float* __restrict__ mw2,
    const float* __restrict__ mw3, const float* __restrict__ mw4,
    const int* __restrict__ receivers, const int* __restrict__ species,
    const float* __restrict__ nf0, const float* __restrict__ nf1,
    const float* __restrict__ wu0, const float* __restrict__ wu1)
{
    __shared__ __align__(16) float smbuf[8704];   // 34.8 KB
    const int b = blockIdx.x;
    const int t = threadIdx.x;

    if (b < EP_BLOCKS) {
        // ---------- edge_pre: 64 edges/block, layers 1-3 -> g_h3 ----------
        float* ha  = smbuf;            // 64*64
        float* hb  = smbuf + 4096;     // 64*64
        float* rad = smbuf + 8192;     // 64*8 = 512 floats

        const int e_base = b * 64;
        rad[t]       = radial[e_base * 8 + t];
        rad[t + 256] = radial[e_base * 8 + t + 256];
        __syncthreads();

        const int j = t & 63;
        const int grp = t >> 6;   // 0..3, 16 edges each

#pragma unroll
        for (int e16 = 0; e16 < 16; e16++) {
            int e = grp * 16 + e16;
            float acc = 0.f;
#pragma unroll
            for (int k = 0; k < 8; k++) acc = fmaf(rad[e * 8 + k], mw1[k * 64 + j], acc);
            ha[e * 64 + j] = silu(acc * INV_SQR);
        }
        __syncthreads();

        {
            float acc[16];
#pragma unroll
            for (int e16 = 0; e16 < 16; e16++) acc[e16] = 0.f;
            for (int k = 0; k < 64; k += 4) {
                float w_0 = mw2[(k + 0) * 64 + j], w_1 = mw2[(k + 1) * 64 + j];
                float w_2 = mw2[(k + 2) * 64 + j], w_3 = mw2[(k + 3) * 64 + j];
#pragma unroll
                for (int e16 = 0; e16 < 16; e16++) {
                    float4 h = *(const float4*)&ha[(grp * 16 + e16) * 64 + k];
                    FMA4(acc[e16], h, w_0, w_1, w_2, w_3);
                }
            }
#pragma unroll
            for (int e16 = 0; e16 < 16; e16++)
                hb[(grp * 16 + e16) * 64 + j] = silu(acc[e16] * 0.125f);
        }
        __syncthreads();

        {
            float acc[16];
#pragma unroll
            for (int e16 = 0; e16 < 16; e16++) acc[e16] = 0.f;
            for (int k = 0; k < 64; k += 4) {
                float w_0 = mw3[(k + 0) * 64 + j], w_1 = mw3[(k + 1) * 64 + j];
                float w_2 = mw3[(k + 2) * 64 + j], w_3 = mw3[(k + 3) * 64 + j];
#pragma unroll
                for (int e16 = 0; e16 < 16; e16++) {
                    float4 h = *(const float4*)&hb[(grp * 16 + e16) * 64 + k];
                    FMA4(acc[e16], h, w_0, w_1, w_2, w_3);
                }
            }
#pragma unroll
            for (int e16 = 0; e16 < 16; e16++)
                g_h3[(e_base + grp * 16 + e16) * 64 + j] = silu(acc[e16] * 0.125f);
        }
    } else if (b < EP_BLOCKS + RF_BLOCKS) {
        // ---------- rfill ----------
        int i = (b - EP_BLOCKS) * 256 + t;
        if (i < NE) {
            int r = receivers[i];
            int pos = g_roff[r] + atomicAdd(&g_rfill[r], 1);
            g_eorder[pos] = i;
        }
    } else if (b < EP_BLOCKS + RF_BLOCKS + W4_BLOCKS) {
        // ---------- w4prep: packed bf16 hi/lo, k pairs ----------
        int i = (b - EP_BLOCKS - RF_BLOCKS) * 256 + t;
        if (i < 32 * 640) {
            int k2 = i / 640, n = i % 640;
            float v0 = mw4[(2 * k2) * 640 + n];
            float v1 = mw4[(2 * k2 + 1) * 640 + n];
            uint32_t h = pack_bf16x2(v0, v1);
            float h0 = __uint_as_float(h << 16);
            float h1 = __uint_as_float(h & 0xffff0000u);
            uint32_t l = pack_bf16x2(v0 - h0, v1 - h1);
            g_w4bh[i] = h;
            g_w4bl[i] = l;
        }
    } else if (b < EP_BLOCKS + RF_BLOCKS + W4_BLOCKS + FS_BLOCKS) {
        // ---------- species fill ----------
        int i = (b - EP_BLOCKS - RF_BLOCKS - W4_BLOCKS) * 256 + t;
        if (i < NN) {
            int sp = species[i];
            int pos = g_off[sp] + atomicAdd(&g_fill[sp], 1);
            g_bucket[pos] = i;
        }
    } else {
        // ---------- linear_up: 8 nodes/block ----------
        float* s0 = smbuf;               // 8*128 = 1024
        float* s1x = smbuf + 1024;
        float* s1y = smbuf + 2048;
        float* s1z = smbuf + 3072;

        const int ub = b - (EP_BLOCKS + RF_BLOCKS + W4_BLOCKS + FS_BLOCKS);
        const int n0 = ub * 8;

        for (int idx = t; idx < 8 * 128; idx += 256) s0[idx] = nf0[n0 * 128 + idx];
        for (int idx = t; idx < 8 * 384; idx += 256) {
            int n = idx / 384, rem = idx % 384;
            int f = rem / 3, c = rem % 3;
            float v = nf1[n0 * 384 + idx];
            if (c == 0) s1x[n * 128 + f] = v;
            else if (c == 1) s1y[n * 128 + f] = v;
            else s1z[n * 128 + f] = v;
        }
        __syncthreads();

        const int ch = t & 127;
        const int h = t >> 7;

        float a0[4], ax[4], ay[4], az[4];
#pragma unroll
        for (int j = 0; j < 4; j++) { a0[j] = ax[j] = ay[j] = az[j] = 0.f; }

        for (int f = 0; f < 128; f += 4) {
            float wA0 = wu0[(f + 0) * 128 + ch], wA1 = wu0[(f + 1) * 128 + ch];
            float wA2 = wu0[(f + 2) * 128 + ch], wA3 = wu0[(f + 3) * 128 + ch];
            float wB0 = wu1[(f + 0) * 128 + ch], wB1 = wu1[(f + 1) * 128 + ch];
            float wB2 = wu1[(f + 2) * 128 + ch], wB3 = wu1[(f + 3) * 128 + ch];
#pragma unroll
            for (int j = 0; j < 4; j++) {
                int jj = h * 4 + j;
                float4 q0 = *(const float4*)&s0[jj * 128 + f];
                FMA4(a0[j], q0, wA0, wA1, wA2, wA3);
                float4 qx = *(const float4*)&s1x[jj * 128 + f];
                FMA4(ax[j], qx, wB0, wB1, wB2, wB3);
                float4 qy = *(const float4*)&s1y[jj * 128 + f];
                FMA4(ay[j], qy, wB0, wB1, wB2, wB3);
                float4 qz = *(const float4*)&s1z[jj * 128 + f];
                FMA4(az[j], qz, wB0, wB1, wB2, wB3);
            }
        }
#pragma unroll
        for (int j = 0; j < 4; j++) {
            int n = n0 + h * 4 + j;
            g_x0[n * 128 + ch] = a0[j] * INV_SQF;
            X1(0, n * 128 + ch) = ax[j] * INV_SQF;
            X1(1, n * 128 + ch) = ay[j] * INV_SQF;
            X1(2, n * 128 + ch) = az[j] * INV_SQF;
        }
    }
}

// ---------------- edge_mma: bf16 3-pass layer4 (R15 shape + hoisted gathers) --
#define APH_OFF 0
#define APL_OFF 4608
#define B_OFF   9216
#define B_HALF  20736                    // 8*648*4
#define B_BUF   41472                    // hi+lo
#define CS_OFF  9216
#define META_OFF 92160
#define EMM_SMEM (META_OFF + 384 + 128 + 128 + 128)

__global__ void __launch_bounds__(512, 2) edge_mma_kernel(
    const float* __restrict__ vectors,
    const int* __restrict__ senders, const int* __restrict__ receivers)
{
    extern __shared__ char smem[];
    uint32_t* APH = (uint32_t*)(smem + APH_OFF);
    uint32_t* APL = (uint32_t*)(smem + APL_OFF);
    float*    CS  = (float*)(smem + CS_OFF);
    float*    y1s = (float*)(smem + META_OFF);
    int*      snd = (int*)(smem + META_OFF + 384);
    int*      rcv = (int*)(smem + META_OFF + 384 + 128);
    int*      eord = (int*)(smem + META_OFF + 384 + 256);

    const int t = threadIdx.x;
    const int e_base = blockIdx.x * 32;
    const uint32_t smem_u32 = (uint32_t)__cvta_generic_to_shared(smem);

    if (t < 32) {
        int oe = g_eorder[e_base + t];
        eord[t] = oe;
        snd[t] = senders[oe];
        rcv[t] = receivers[oe];
        float vx = vectors[oe * 3 + 0], vy = vectors[oe * 3 + 1], vz = vectors[oe * 3 + 2];
        float rn = sqrtf(vx * vx + vy * vy + vz * vz) + 1e-12f;
        float sc = SQ3f / rn;
        y1s[t * 3 + 0] = vx * sc;
        y1s[t * 3 + 1] = vy * sc;
        y1s[t * 3 + 2] = vz * sc;
    }
    __syncthreads();

#pragma unroll
    for (int i = 0; i < 2; i++) {
        int idx = t + i * 512;
        int r = idx >> 5, k2 = idx & 31;
        float2 p = *(const float2*)&g_h3[eord[r] * 64 + 2 * k2];
        uint32_t h = pack_bf16x2(p.x, p.y);
        float h0 = __uint_as_float(h << 16);
        float h1 = __uint_as_float(h & 0xffff0000u);
        uint32_t l = pack_bf16x2(p.x - h0, p.y - h1);
        APH[r * 36 + k2] = h;
        APL[r * 36 + k2] = l;
    }

    {
#pragma unroll
        for (int i = 0; i < 3; i++) {
            int idx = t + i * 512;
            if (idx < 1280) {
                int r = idx / 160, c = idx % 160;
                uint32_t dh = smem_u32 + B_OFF + (r * 648 + c * 4) * 4;
                cp_async16(dh, g_w4bh + r * 640 + c * 4);
                cp_async16(dh + B_HALF, g_w4bl + r * 640 + c * 4);
            }
        }
        cp_commit();
    }

    const int warp = t >> 5;
    const int lane = t & 31;
    const int g = lane >> 2;
    const int q = lane & 3;
    const int wm = warp & 1;
    const int wn = warp >> 1;
    const int r0 = wm * 16 + g;

    float acc[10][4];
#pragma unroll
    for (int nt = 0; nt < 10; nt++)
#pragma unroll
        for (int i = 0; i < 4; i++) acc[nt][i] = 0.f;

    for (int s = 0; s < 4; s++) {
        if (s + 1 < 4) {
            const int buf = (s + 1) & 1;
#pragma unroll
            for (int i = 0; i < 3; i++) {
                int idx = t + i * 512;
                if (idx < 1280) {
                    int r = idx / 160, c = idx % 160;
                    uint32_t dh = smem_u32 + B_OFF + buf * B_BUF + (r * 648 + c * 4) * 4;
                    cp_async16(dh, g_w4bh + ((s + 1) * 8 + r) * 640 + c * 4);
                    cp_async16(dh + B_HALF, g_w4bl + ((s + 1) * 8 + r) * 640 + c * 4);
                }
            }
            cp_commit();
            cp_wait<1>();
        } else {
            cp_wait<0>();
        }
        __syncthreads();

        const uint32_t* BH = (const uint32_t*)(smem + B_OFF + (s & 1) * B_BUF);
        const uint32_t* BL = BH + B_HALF / 4;

        const int kq = s * 8 + q;
        uint32_t ah0 = APH[r0 * 36 + kq];
        uint32_t ah1 = APH[(r0 + 8) * 36 + kq];
        uint32_t ah2 = APH[r0 * 36 + kq + 4];
        uint32_t ah3 = APH[(r0 + 8) * 36 + kq + 4];
        uint32_t al0 = APL[r0 * 36 + kq];
        uint32_t al1 = APL[(r0 + 8) * 36 + kq];
        uint32_t al2 = APL[r0 * 36 + kq + 4];
        uint32_t al3 = APL[(r0 + 8) * 36 + kq + 4];

#pragma unroll
        for (int nt = 0; nt < 10; nt++) {
            const int nb = wn * 80 + nt * 8 + g;
            uint32_t bh0 = BH[q * 648 + nb];
            uint32_t bh1 = BH[(q + 4) * 648 + nb];
            uint32_t bl0 = BL[q * 648 + nb];
            uint32_t bl1 = BL[(q + 4) * 648 + nb];
            mma_bf16(acc[nt], ah0, ah1, ah2, ah3, bh0, bh1);
            mma_bf16(acc[nt], ah0, ah1, ah2, ah3, bl0, bl1);
            mma_bf16(acc[nt], al0, al1, al2, al3, bh0, bh1);
        }
        __syncthreads();
    }

#pragma unroll
    for (int nt = 0; nt < 10; nt++) {
        int col = wn * 80 + nt * 8 + 2 * q;
        CS[r0 * 644 + col]           = acc[nt][0];
        CS[r0 * 644 + col + 1]       = acc[nt][1];
        CS[(r0 + 8) * 644 + col]     = acc[nt][2];
        CS[(r0 + 8) * 644 + col + 1] = acc[nt][3];
    }
    __syncthreads();

    // ---- message phase: hoisted sender gathers (MLP=32), then compute+flush ----
    const int f = t & 127;
    const int eg = t >> 7;

    float m0a[8], m1xa[8], m1ya[8], m1za[8];
#pragma unroll
    for (int ee = 0; ee < 8; ee++) {
        int sN = snd[eg * 8 + ee];
        m0a[ee]  = g_x0[sN * 128 + f];
        m1xa[ee] = X1(0, sN * 128 + f);
        m1ya[ee] = X1(1, sN * 128 + f);
        m1za[ee] = X1(2, sN * 128 + f);
    }

    float A0 = 0.f, A1x = 0.f, A1y = 0.f, A1z = 0.f;
    int cur = -1;

#pragma unroll
    for (int ee = 0; ee < 8; ee++) {
        int el = eg * 8 + ee;
        int r = rcv[el];
        float m0  = m0a[ee];
        float m1x = m1xa[ee];
        float m1y = m1ya[ee];
        float m1z = m1za[ee];
        float Yx = y1s[el * 3 + 0], Yy = y1s[el * 3 + 1], Yz = y1s[el * 3 + 2];

        const float* crow = CS + el * 644;
        float mix0 = crow[0 * 128 + f] * 0.125f;
        float mix1 = crow[1 * 128 + f] * 0.125f;
        float mix2 = crow[2 * 128 + f] * 0.125f;
        float mix3 = crow[3 * 128 + f] * 0.125f;
        float mix4 = crow[4 * 128 + f] * 0.125f;

        float dotf = (m1x * Yx + m1y * Yy + m1z * Yz) * INV_SQ3;
        float out0 = mix0 * m0 + mix1 * dotf;

        float ox = m0 * Yx * INV_SQ3;
        float oy = m0 * Yy * INV_SQ3;
        float oz = m0 * Yz * INV_SQ3;

        float cx = (m1y * Yz - m1z * Yy) * INV_SQ3;
        float cy = (m1z * Yx - m1x * Yz) * INV_SQ3;
        float cz = (m1x * Yy - m1y * Yx) * INV_SQ3;

        float o1x = mix2 * ox + mix3 * m1x + mix4 * cx;
        float o1y = mix2 * oy + mix3 * m1y + mix4 * cy;
        float o1z = mix2 * oz + mix3 * m1z + mix4 * cz;

        if (r != cur) {
            if (cur >= 0) {
                atomicAdd(&g_a0[cur * 128 + f], EPSf * A0);
                atomicAdd(&A1(0, cur * 128 + f), EPSf * A1x);
                atomicAdd(&A1(1, cur * 128 + f), EPSf * A1y);
                atomicAdd(&A1(2, cur * 128 + f), EPSf * A1z);
            }
            cur = r;
            A0 = A1x = A1y = A1z = 0.f;
        }
        A0 += out0; A1x += o1x; A1y += o1y; A1z += o1z;
    }
    if (cur >= 0) {
        atomicAdd(&g_a0[cur * 128 + f], EPSf * A0);
        atomicAdd(&A1(0, cur * 128 + f), EPSf * A1x);
        atomicAdd(&A1(1, cur * 128 + f), EPSf * A1y);
        atomicAdd(&A1(2, cur * 128 + f), EPSf * A1z);
    }
}

// ---------------- node kernel (R12 proven 128-thread shape) --------------------
__global__ void __launch_bounds__(128) node_kernel(
    const float* __restrict__ nf0, const float* __restrict__ nf1,
    const int* __restrict__ species,
    const float* __restrict__ wz0, const float* __restrict__ wz1,
    const float* __restrict__ wd0, const float* __restrict__ wd1,
    const float* __restrict__ wsc,
    const float* __restrict__ wp0, const float* __restrict__ wp1,
    const float* __restrict__ wr0,
    float* __restrict__ out, int write_feats)
{
    __shared__ __align__(16) float sa0[8 * 128];
    __shared__ __align__(16) float sa1[3][8 * 128];
    __shared__ __align__(16) float sn0[8 * 128];
    __shared__ __align__(16) float sn1[3][8 * 128];
    __shared__ int   snid[8];
    __shared__ int   ssp[8];
    __shared__ float sred[8 * 4];

    const int t = threadIdx.x;
    const int bb = blockIdx.x * 8;

    if (t < 8) {
        int n = g_bucket[bb + t];
        snid[t] = n;
        ssp[t] = species[n];
    }
    __syncthreads();

    bool uni = true;
    int sp0 = ssp[0];
#pragma unroll
    for (int jj = 1; jj < 8; jj++) uni = uni && (ssp[jj] == sp0);

#pragma unroll
    for (int jj = 0; jj < 8; jj++) {
        int n = snid[jj];
        sa0[jj * 128 + t] = g_a0[n * 128 + t];
        sn0[jj * 128 + t] = nf0[n * 128 + t];
#pragma unroll
        for (int c = 0; c < 3; c++) {
            sa1[c][jj * 128 + t] = A1(c, n * 128 + t);
            sn1[c][jj * 128 + t] = nf1[(n * 128 + t) * 3 + c];
        }
    }
    __syncthreads();

    float s[8], vx[8], vy[8], vz[8];
#pragma unroll
    for (int jj = 0; jj < 8; jj++) { s[jj] = vx[jj] = vy[jj] = vz[jj] = 0.f; }

    for (int f = 0; f < 128; f += 4) {
        float wA0 = wd0[(f + 0) * 128 + t], wA1 = wd0[(f + 1) * 128 + t];
        float wA2 = wd0[(f + 2) * 128 + t], wA3 = wd0[(f + 3) * 128 + t];
        float wB0 = wd1[(f + 0) * 128 + t], wB1 = wd1[(f + 1) * 128 + t];
        float wB2 = wd1[(f + 2) * 128 + t], wB3 = wd1[(f + 3) * 128 + t];
#pragma unroll
        for (int jj = 0; jj < 8; jj++) {
            float4 q0 = *(const float4*)&sa0[jj * 128 + f];
            FMA4(s[jj], q0, wA0, wA1, wA2, wA3);
            float4 qx = *(const float4*)&sa1[0][jj * 128 + f];
            FMA4(vx[jj], qx, wB0, wB1, wB2, wB3);
            float4 qy = *(const float4*)&sa1[1][jj * 128 + f];
            FMA4(vy[jj], qy, wB0, wB1, wB2, wB3);
            float4 qz = *(const float4*)&sa1[2][jj * 128 + f];
            FMA4(vz[jj], qz, wB0, wB1, wB2, wB3);
        }
    }

    float c0[8], cx[8], cy[8], cz[8];
#pragma unroll
    for (int jj = 0; jj < 8; jj++) { c0[jj] = cx[jj] = cy[jj] = cz[jj] = 0.f; }

    if (uni) {
        const float* z0 = wz0 + sp0 * (128 * 128);
        const float* z1 = wz1 + sp0 * (128 * 128);
        for (int f = 0; f < 128; f += 4) {
            float zA0 = z0[(f + 0) * 128 + t], zA1 = z0[(f + 1) * 128 + t];
            float zA2 = z0[(f + 2) * 128 + t], zA3 = z0[(f + 3) * 128 + t];
            float zB0 = z1[(f + 0) * 128 + t], zB1 = z1[(f + 1) * 128 + t];
            float zB2 = z1[(f + 2) * 128 + t], zB3 = z1[(f + 3) * 128 + t];
#pragma unroll
            for (int jj = 0; jj < 8; jj++) {
                float4 q0 = *(const float4*)&sn0[jj * 128 + f];
                FMA4(c0[jj], q0, zA0, zA1, zA2, zA3);
                float4 qx = *(const float4*)&sn1[0][jj * 128 + f];
                FMA4(cx[jj], qx, zB0, zB1, zB2, zB3);
                float4 qy = *(const float4*)&sn1[1][jj * 128 + f];
                FMA4(cy[jj], qy, zB0, zB1, zB2, zB3);
                float4 qz = *(const float4*)&sn1[2][jj * 128 + f];
                FMA4(cz[jj], qz, zB0, zB1, zB2, zB3);
            }
        }
    } else {
        for (int jj = 0; jj < 8; jj++) {
            const float* z0 = wz0 + ssp[jj] * (128 * 128);
            const float* z1 = wz1 + ssp[jj] * (128 * 128);
            for (int f = 0; f < 128; f += 4) {
                float zA0 = z0[(f + 0) * 128 + t], zA1 = z0[(f + 1) * 128 + t];
                float zA2 = z0[(f + 2) * 128 + t], zA3 = z0[(f + 3) * 128 + t];
                float zB0 = z1[(f + 0) * 128 + t], zB1 = z1[(f + 1) * 128 + t];
                float zB2 = z1[(f + 2) * 128 + t], zB3 = z1[(f + 3) * 128 + t];
                float4 q0 = *(const float4*)&sn0[jj * 128 + f];
                FMA4(c0[jj], q0, zA0, zA1, zA2, zA3);
                float4 qx = *(const float4*)&sn1[0][jj * 128 + f];
                FMA4(cx[jj], qx, zB0, zB1, zB2, zB3);
                float4 qy = *(const float4*)&sn1[1][jj * 128 + f];
                FMA4(cy[jj], qy, zB0, zB1, zB2, zB3);
                float4 qz = *(const float4*)&sn1[2][jj * 128 + f];
                FMA4(cz[jj], qz, zB0, zB1, zB2, zB3);
            }
        }
    }
    __syncthreads();

#pragma unroll
    for (int jj = 0; jj < 8; jj++) {
        sn0[jj * 128 + t]    = c0[jj];
        sn1[0][jj * 128 + t] = cx[jj];
        sn1[1][jj * 128 + t] = cy[jj];
        sn1[2][jj * 128 + t] = cz[jj];
    }

#pragma unroll
    for (int jj = 0; jj < 8; jj++) {
        float sv  = s[jj] * INV_SQF;
        float vxx = vx[jj] * INV_SQF;
        float vyy = vy[jj] * INV_SQF;
        float vzz = vz[jj] * INV_SQF;
        float vv  = vxx * vxx + vyy * vyy + vzz * vzz;
        const float* w = wsc + ssp[jj] * (9 * 128);
        float w0 = w[0 * 128 + t] * INV_SQZ;
        float w1 = w[1 * 128 + t] * INV_SQZ;
        float w2 = w[2 * 128 + t] * INV_SQZ;
        float w3 = w[3 * 128 + t] * INV_SQZ;
        float w4 = w[4 * 128 + t] * INV_SQZ;
        float w5 = w[5 * 128 + t] * INV_SQZ;
        float w6 = w[6 * 128 + t] * INV_SQZ;
        float w7 = w[7 * 128 + t] * INV_SQZ;
        float w8 = w[8 * 128 + t] * INV_SQZ;
        float b0v = w0 * sv + w1 * sv * sv + w2 * vv + w3 * sv * sv * sv + w4 * sv * vv;
        float g1  = w5 + w6 * sv + w7 * sv * sv + w8 * vv;
        sa0[jj * 128 + t]    = b0v;
        sa1[0][jj * 128 + t] = g1 * vxx;
        sa1[1][jj * 128 + t] = g1 * vyy;
        sa1[2][jj * 128 + t] = g1 * vzz;
    }
    __syncthreads();

    float f0[8], f1x[8], f1y[8], f1z[8];
#pragma unroll
    for (int jj = 0; jj < 8; jj++) { f0[jj] = f1x[jj] = f1y[jj] = f1z[jj] = 0.f; }

    for (int f = 0; f < 128; f += 4) {
        float wA0 = wp0[(f + 0) * 128 + t], wA1 = wp0[(f + 1) * 128 + t];
        float wA2 = wp0[(f + 2) * 128 + t], wA3 = wp0[(f + 3) * 128 + t];
        float wB0 = wp1[(f + 0) * 128 + t], wB1 = wp1[(f + 1) * 128 + t];
        float wB2 = wp1[(f + 2) * 128 + t], wB3 = wp1[(f + 3) * 128 + t];
#pragma unroll
        for (int jj = 0; jj < 8; jj++) {
            float4 q0 = *(const float4*)&sa0[jj * 128 + f];
            FMA4(f0[jj], q0, wA0, wA1, wA2, wA3);
            float4 qx = *(const float4*)&sa1[0][jj * 128 + f];
            FMA4(f1x[jj], qx, wB0, wB1, wB2, wB3);
            float4 qy = *(const float4*)&sa1[1][jj * 128 + f];
            FMA4(f1y[jj], qy, wB0, wB1, wB2, wB3);
            float4 qz = *(const float4*)&sa1[2][jj * 128 + f];
            FMA4(f1z[jj], qz, wB0, wB1, wB2, wB3);
        }
    }

    float wrv = wr0[t];
#pragma unroll
    for (int jj = 0; jj < 8; jj++) {
        int n = snid[jj];
        float F0  = f0[jj]  * INV_SQF + sn0[jj * 128 + t]    * INV_SQFZ;
        float F1x = f1x[jj] * INV_SQF + sn1[0][jj * 128 + t] * INV_SQFZ;
        float F1y = f1y[jj] * INV_SQF + sn1[1][jj * 128 + t] * INV_SQFZ;
        float F1z = f1z[jj] * INV_SQF + sn1[2][jj * 128 + t] * INV_SQFZ;

        if (write_feats) {
            out[NN + n * 128 + t]                      = F0;
            out[NN + NN * 128 + (n * 128 + t) * 3 + 0] = F1x;
            out[NN + NN * 128 + (n * 128 + t) * 3 + 1] = F1y;
            out[NN + NN * 128 + (n * 128 + t) * 3 + 2] = F1z;
        }

        float contrib = F0 * wrv;
#pragma unroll
        for (int off = 16; off > 0; off >>= 1)
            contrib += __shfl_xor_sync(0xffffffffu, contrib, off);
        if ((t & 31) == 0) sred[jj * 4 + (t >> 5)] = contrib;
    }
    __syncthreads();
    if (t < 8) {
        float r = (sred[t * 4 + 0] + sred[t * 4 + 1] + sred[t * 4 + 2] + sred[t * 4 + 3]) * INV_SQF;
        out[snid[t]] = r;
    }
}

// ---------------- launch ------------------------------------------------------
extern "C" void kernel_launch(void* const* d_in, const int* in_sizes, int n_in,
                              void* d_out, int out_size)
{
    const float* vectors   = (const float*)d_in[0];
    const float* nf0       = (const float*)d_in[1];
    const float* nf1       = (const float*)d_in[2];
    const float* radial    = (const float*)d_in[3];
    const int*   species   = (const int*)d_in[4];
    const int*   senders   = (const int*)d_in[5];
    const int*   receivers = (const int*)d_in[6];
    const float* wz0       = (const float*)d_in[7];
    const float* wz1       = (const float*)d_in[8];
    const float* wu0       = (const float*)d_in[9];
    const float* wu1       = (const float*)d_in[10];
    const float* mw1       = (const float*)d_in[11];
    const float* mw2       = (const float*)d_in[12];
    const float* mw3       = (const float*)d_in[13];
    const float* mw4       = (const float*)d_in[14];
    const float* wd0       = (const float*)d_in[15];
    const float* wd1       = (const float*)d_in[16];
    const float* wsc       = (const float*)d_in[17];
    const float* wp0       = (const float*)d_in[18];
    const float* wp1       = (const float*)d_in[19];
    const float* wr0       = (const float*)d_in[20];
    float* out = (float*)d_out;

    int write_feats = (out_size >= NN * (1 + 4 * FF)) ? 1 : 0;

    cudaFuncSetAttribute(edge_mma_kernel,
                         cudaFuncAttributeMaxDynamicSharedMemorySize, EMM_SMEM);

    setup0_kernel<<<1024, 256>>>();                                 // 1
    setup1_kernel<<<512, 256>>>(receivers, species);                // 2
    setup2_kernel<<<1, 1024>>>();                                   // 3
    mega_kernel<<<MEGA_BLOCKS, 256>>>(radial, mw1, mw2, mw3, mw4,
                                      receivers, species, nf0, nf1,
                                      wu0, wu1);                    // 4 <- ncu
    edge_mma_kernel<<<NE / 32, 512, EMM_SMEM>>>(vectors, senders, receivers); // 5
    node_kernel<<<NN / 8, 128>>>(nf0, nf1, species, wz0, wz1, wd0, wd1,
                                 wsc, wp0, wp1, wr0, out, write_feats);       // 6
}